// round 1
// baseline (speedup 1.0000x reference)
#include <cuda_runtime.h>

// Lanczos upsample (4,2,256,256) f32 -> (4,2,2048,2048) f32, factor 8 each axis.
//
// The reference nearest-gathers to the 2048 grid, then applies a 9-tap
// LUT-Lanczos filter per axis on the UPSAMPLED grid. Because the gathered
// signal is constant within 8-blocks, the 9 taps hit at most 2 source pixels,
// and the weights depend only on phase f = coord & 7. Reflect padding at the
// edges maps every out-of-range tap to the boundary source pixel (== clamp).
// => out[y,x] = (Ay,By) x (Ax,Bx) 2x2 weighted gather of the 256x256 source.

#define PI_F 3.14159265358979323846f

__device__ float g_wA[8];
__device__ float g_wB[8];

// Compute the 8 phase weight pairs once. Matches the reference's float32
// table: delta = 1e-8 + f/8 (LUT index f*128), taps t = delta + (p-4),
// w = sinc(t)*sinc(t/4). Taps p < 8-r belong to source c0 (r = (f+4)&7).
__global__ void lz_init_weights() {
    int f = threadIdx.x;
    if (f >= 8) return;
    float delta = 1e-8f + (float)f * 0.125f;
    int r = (f + 4) & 7;
    float A = 0.f, B = 0.f;
#pragma unroll
    for (int p = 0; p < 9; ++p) {
        float t  = delta + (float)(p - 4);
        float tp = t * PI_F;
        float tq = tp * 0.25f;
        float w  = (sinf(tp) / tp) * (sinf(tq) / tq);
        if (p < 8 - r) A += w; else B += w;
    }
    g_wA[f] = A;
    g_wB[f] = B;
}

// One block = one output row (2048 px = 8 KB). Thread k computes the aligned
// 8-pixel phase cycle x = 8k..8k+7, needing source columns k-1,k,k+1 from the
// two source rows ry0/ry1. Two STG.128 per thread, fully coalesced.
__global__ void __launch_bounds__(256)
lz_upsample_kernel(const float* __restrict__ img, float* __restrict__ out) {
    const int row = blockIdx.x;          // 0..16383 : (b*C+c)*2048 + y
    const int bc  = row >> 11;           // image-channel index 0..7
    const int y   = row & 2047;

    const int fy   = y & 7;
    const int ry0u = (y - 4) >> 3;       // arithmetic shift; -1 at top edge
    const int ry0  = max(ry0u, 0);
    const int ry1  = min(ry0u + 1, 255);

    const float Ay = g_wA[fy];
    const float By = g_wB[fy];

    const float* __restrict__ base = img + (size_t)bc * 65536;
    const float* __restrict__ r0   = base + ry0 * 256;
    const float* __restrict__ r1   = base + ry1 * 256;

    const int k  = threadIdx.x;          // source column / x-block index
    const int km = max(k - 1, 0);
    const int kp = min(k + 1, 255);

    // Vertical pass folded in: v_i = Ay*img[ry0,ci] + By*img[ry1,ci]
    const float v0 = Ay * __ldg(r0 + km) + By * __ldg(r1 + km);
    const float v1 = Ay * __ldg(r0 + k)  + By * __ldg(r1 + k);
    const float v2 = Ay * __ldg(r0 + kp) + By * __ldg(r1 + kp);

    float wa[8], wb[8];
#pragma unroll
    for (int f = 0; f < 8; ++f) { wa[f] = g_wA[f]; wb[f] = g_wB[f]; }

    // Phases 0..3: sources (k-1, k); phases 4..7: sources (k, k+1).
    float4 o0, o1;
    o0.x = wa[0] * v0 + wb[0] * v1;
    o0.y = wa[1] * v0 + wb[1] * v1;
    o0.z = wa[2] * v0 + wb[2] * v1;
    o0.w = wa[3] * v0 + wb[3] * v1;
    o1.x = wa[4] * v1 + wb[4] * v2;
    o1.y = wa[5] * v1 + wb[5] * v2;
    o1.z = wa[6] * v1 + wb[6] * v2;
    o1.w = wa[7] * v1 + wb[7] * v2;

    float4* op = reinterpret_cast<float4*>(out + (size_t)row * 2048 + k * 8);
    op[0] = o0;
    op[1] = o1;
}

extern "C" void kernel_launch(void* const* d_in, const int* in_sizes, int n_in,
                              void* d_out, int out_size) {
    (void)in_sizes; (void)n_in; (void)out_size;
    const float* img = (const float*)d_in[0];
    float* out = (float*)d_out;

    lz_init_weights<<<1, 8>>>();
    lz_upsample_kernel<<<16384, 256>>>(img, out);
}

// round 2
// speedup vs baseline: 1.0598x; 1.0598x over previous
#include <cuda_runtime.h>

// Lanczos upsample (4,2,256,256) f32 -> (4,2,2048,2048) f32, 8x per axis.
//
// Algebra (validated round 1, rel_err 1.5e-7): the reference's nearest-gather +
// 9-tap LUT-Lanczos on the upsampled grid collapses to a 2x2 weighted gather of
// the source with 8 phase-dependent weight pairs per axis; reflect padding ==
// clamp to the boundary source pixel.
//
// This round: weights are computed at COMPILE TIME (constexpr double sin), so
// x-phase weights are FFMA immediates and y-weights are 2 uniform LDCs --
// removing the 16 per-thread global weight loads that made round 1 LSU-bound.

namespace lw {

constexpr double PI = 3.14159265358979323846;

// constexpr sin: reduce to [-pi/2, pi/2], 11-term Taylor (|err| < 1e-15 here).
constexpr double csin(double x) {
    double k = x / (2.0 * PI);
    long long n = (long long)(k >= 0.0 ? k + 0.5 : k - 0.5);
    double r = x - (double)n * (2.0 * PI);
    if (r > PI * 0.5)       r =  PI - r;
    else if (r < -PI * 0.5) r = -PI - r;
    double term = r, sum = r;
    const double r2 = r * r;
    for (int i = 1; i <= 11; ++i) {
        term *= -r2 / ((2.0 * i) * (2.0 * i + 1.0));
        sum += term;
    }
    return sum;
}

// Lanczos(a=4) tap value at t = delta + (p-4):  sinc(pi t) * sinc(pi t / 4)
constexpr double tap(double d, int p) {
    double t  = d + (double)(p - 4);
    double tp = t * PI;
    double tq = tp * 0.25;
    return (csin(tp) / tp) * (csin(tq) / tq);
}

// Phase f (delta = 1e-8 + f/8): taps p < 8-r hit source c0, rest hit c1,
// where r = (f+4)&7.  (Same split as the round-1 device init kernel.)
constexpr float wA(int f) {
    double d = 1e-8 + (double)f / 8.0;
    int r = (f + 4) & 7;
    double a = 0.0;
    for (int p = 0; p < 8 - r; ++p) a += tap(d, p);
    return (float)a;
}
constexpr float wB(int f) {
    double d = 1e-8 + (double)f / 8.0;
    int r = (f + 4) & 7;
    double b = 0.0;
    for (int p = 8 - r; p <= 8; ++p) b += tap(d, p);
    return (float)b;
}

} // namespace lw

// x-phase weights: compile-time literals -> FFMA immediates in SASS.
constexpr float A0 = lw::wA(0), A1 = lw::wA(1), A2 = lw::wA(2), A3 = lw::wA(3);
constexpr float A4 = lw::wA(4), A5 = lw::wA(5), A6 = lw::wA(6), A7 = lw::wA(7);
constexpr float B0 = lw::wB(0), B1 = lw::wB(1), B2 = lw::wB(2), B3 = lw::wB(3);
constexpr float B4 = lw::wB(4), B5 = lw::wB(5), B6 = lw::wB(6), B7 = lw::wB(7);

// y weights need a runtime index (row & 7): constant bank, uniform per block.
__constant__ float c_wA[8] = {A0, A1, A2, A3, A4, A5, A6, A7};
__constant__ float c_wB[8] = {B0, B1, B2, B3, B4, B5, B6, B7};

// One block = one output row (2048 px = 8 KB). Thread k computes the aligned
// 8-pixel phase cycle x = 8k..8k+7 from source columns k-1,k,k+1 of the two
// source rows. Two streaming STG.128 per thread, fully coalesced.
__global__ void __launch_bounds__(256)
lz_upsample_kernel(const float* __restrict__ img, float* __restrict__ out) {
    const int row = blockIdx.x;          // (b*C+c)*2048 + y
    const int bc  = row >> 11;
    const int y   = row & 2047;

    const int fy   = y & 7;
    const int ry0u = (y - 4) >> 3;       // arithmetic shift; -1 at top edge
    const int ry0  = max(ry0u, 0);
    const int ry1  = min(ry0u + 1, 255);

    const float Ay = c_wA[fy];
    const float By = c_wB[fy];

    const float* __restrict__ base = img + (size_t)bc * 65536;
    const float* __restrict__ r0   = base + ry0 * 256;
    const float* __restrict__ r1   = base + ry1 * 256;

    const int k  = threadIdx.x;          // source column / x-block index
    const int km = max(k - 1, 0);
    const int kp = min(k + 1, 255);

    // Vertical pass folded in: v_i = Ay*img[ry0,ci] + By*img[ry1,ci]
    const float v0 = Ay * __ldg(r0 + km) + By * __ldg(r1 + km);
    const float v1 = Ay * __ldg(r0 + k)  + By * __ldg(r1 + k);
    const float v2 = Ay * __ldg(r0 + kp) + By * __ldg(r1 + kp);

    // Phases 0..3: sources (k-1, k); phases 4..7: sources (k, k+1).
    float4 o0, o1;
    o0.x = A0 * v0 + B0 * v1;
    o0.y = A1 * v0 + B1 * v1;
    o0.z = A2 * v0 + B2 * v1;
    o0.w = A3 * v0 + B3 * v1;
    o1.x = A4 * v1 + B4 * v2;
    o1.y = A5 * v1 + B5 * v2;
    o1.z = A6 * v1 + B6 * v2;
    o1.w = A7 * v1 + B7 * v2;

    float4* op = reinterpret_cast<float4*>(out + (size_t)row * 2048 + k * 8);
    __stcs(op,     o0);   // streaming: output (134MB) won't be re-read
    __stcs(op + 1, o1);
}

extern "C" void kernel_launch(void* const* d_in, const int* in_sizes, int n_in,
                              void* d_out, int out_size) {
    (void)in_sizes; (void)n_in; (void)out_size;
    const float* img = (const float*)d_in[0];
    float* out = (float*)d_out;

    lz_upsample_kernel<<<16384, 256>>>(img, out);
}